// round 5
// baseline (speedup 1.0000x reference)
#include <cuda_runtime.h>
#include <cuda_bf16.h>
#include <cstdint>
#include <math.h>

#define D_MODEL 2048
#define N_EXP   64
#define TOP_K   8
#define SCALE   0.022097086912079608f
#define EPS     4e-6f
#define MAX_T   16384

#define CTA_TOK 128
#define KCHUNK  64
#define NCHUNK  (D_MODEL / KCHUNK)   // 32
#define WROWB   144                  // padded bytes per W smem row (72 bf16)
#define LROW    66                   // padded floats per logit row

// SMEM layout (static, 37120 B < 48KB):
//   [0      .. 36864)  W stages: 2 stages x (hi plane 9216 + lo plane 9216)
//                      (aliased by logits scratch in the epilogue: 8*16*66*4 = 33792)
//   [36864  .. 37120)  bias (64 floats)
#define SM_WHI(s)  ((s) * 18432)
#define SM_WLO(s)  ((s) * 18432 + 9216)
#define SM_BIAS    36864
#define SM_TOTAL   37120

// ---- flag scratch ----------------------------------------------------------
__device__ int g_flag_count;
__device__ int g_flags[MAX_T];

__global__ void zero_flags_kernel() { g_flag_count = 0; }

// ---- helpers ---------------------------------------------------------------
static __device__ __forceinline__ uint32_t bpack(float x, float y) {
    __nv_bfloat162 t = __floats2bfloat162_rn(x, y);
    return *reinterpret_cast<uint32_t*>(&t);
}

// pack hi (bf16 of x,y) and lo (bf16 of residuals)
static __device__ __forceinline__ void split2(float x, float y,
                                              uint32_t& hi, uint32_t& lo) {
    __nv_bfloat162 h = __floats2bfloat162_rn(x, y);
    hi = *reinterpret_cast<uint32_t*>(&h);
    float rx = x - __bfloat162float(h.x);
    float ry = y - __bfloat162float(h.y);
    lo = bpack(rx, ry);
}

static __device__ __forceinline__ void mma16816(float* d, const uint32_t* a,
                                                uint32_t b0, uint32_t b1) {
    asm volatile(
        "mma.sync.aligned.m16n8k16.row.col.f32.bf16.bf16.f32 "
        "{%0,%1,%2,%3}, {%4,%5,%6,%7}, {%8,%9}, {%0,%1,%2,%3};"
        : "+f"(d[0]), "+f"(d[1]), "+f"(d[2]), "+f"(d[3])
        : "r"(a[0]), "r"(a[1]), "r"(a[2]), "r"(a[3]), "r"(b0), "r"(b1));
}

// ---------------------------------------------------------------------------
// Main kernel: 3-pass bf16-split HMMA GEMM + fused top-k/softmax epilogue.
// 8 warps; warp = 16 tokens x 64 experts. W tiles staged in SMEM (bf16 hi/lo,
// double buffered); x fragments loaded gmem->reg directly (zero reuse).
// ---------------------------------------------------------------------------
__global__ void __launch_bounds__(256, 1)
router_mma_kernel(const float* __restrict__ x, const float* __restrict__ W,
                  const float* __restrict__ bias, float* __restrict__ out, int T)
{
    __shared__ char sm[SM_TOTAL];

    const int tid  = threadIdx.x;
    const int wid  = tid >> 5;
    const int lane = tid & 31;
    const int tokBase = blockIdx.x * CTA_TOK;
    const int wtok = tokBase + wid * 16;

    float* bias_sm = reinterpret_cast<float*>(sm + SM_BIAS);
    if (tid < N_EXP) bias_sm[tid] = bias[tid];

    // ---- W chunk loader: 4096 floats per chunk, 4 float4 per thread --------
    // u = tid + 256*j : n = u>>4 (expert row), kq = u&15 (float4 within row)
    auto load_chunk = [&](int c, float4* r) {
#pragma unroll
        for (int j = 0; j < 4; j++) {
            int u  = tid + 256 * j;
            int n  = u >> 4;
            int kq = u & 15;
            r[j] = *reinterpret_cast<const float4*>(
                W + (size_t)n * D_MODEL + c * KCHUNK + kq * 4);
        }
    };
    auto store_chunk = [&](int s, const float4* r) {
#pragma unroll
        for (int j = 0; j < 4; j++) {
            int u  = tid + 256 * j;
            int n  = u >> 4;
            int kq = u & 15;
            uint32_t h01, l01, h23, l23;
            split2(r[j].x, r[j].y, h01, l01);
            split2(r[j].z, r[j].w, h23, l23);
            uint32_t off = (uint32_t)n * WROWB + kq * 8;
            *reinterpret_cast<uint2*>(sm + SM_WHI(s) + off) = make_uint2(h01, h23);
            *reinterpret_cast<uint2*>(sm + SM_WLO(s) + off) = make_uint2(l01, l23);
        }
    };

    // prologue: stage chunk 0
    {
        float4 r[4];
        load_chunk(0, r);
        store_chunk(0, r);
    }
    __syncthreads();

    // accumulators: 8 n-tiles x 4 fp32
    float d[8][4];
#pragma unroll
    for (int j = 0; j < 8; j++)
#pragma unroll
        for (int q = 0; q < 4; q++) d[j][q] = 0.0f;

    const int rA = lane >> 2;          // fragment row
    const int cp = (lane & 3) << 1;    // fragment col pair
    const float* xA = x + (size_t)(wtok + rA) * D_MODEL;
    const float* xB = x + (size_t)(wtok + rA + 8) * D_MODEL;
    const uint32_t bfoff = (uint32_t)(lane >> 2) * WROWB + (uint32_t)(lane & 3) * 4;

    for (int c = 0; c < NCHUNK; c++) {
        const int s = c & 1;
        float4 wreg[4];
        if (c + 1 < NCHUNK) load_chunk(c + 1, wreg);

#pragma unroll
        for (int ks = 0; ks < 4; ks++) {
            const int kg = c * KCHUNK + ks * 16;

            // A fragments (hi/lo) straight from gmem
            float2 f0 = *reinterpret_cast<const float2*>(xA + kg + cp);
            float2 f1 = *reinterpret_cast<const float2*>(xB + kg + cp);
            float2 f2 = *reinterpret_cast<const float2*>(xA + kg + cp + 8);
            float2 f3 = *reinterpret_cast<const float2*>(xB + kg + cp + 8);
            uint32_t ahi[4], alo[4];
            split2(f0.x, f0.y, ahi[0], alo[0]);
            split2(f1.x, f1.y, ahi[1], alo[1]);
            split2(f2.x, f2.y, ahi[2], alo[2]);
            split2(f3.x, f3.y, ahi[3], alo[3]);

            const char* whi = sm + SM_WHI(s) + ks * 32 + bfoff;
            const char* wlo = sm + SM_WLO(s) + ks * 32 + bfoff;
#pragma unroll
            for (int j = 0; j < 8; j++) {
                uint32_t roff = (uint32_t)j * 8 * WROWB;
                uint32_t bh0 = *reinterpret_cast<const uint32_t*>(whi + roff);
                uint32_t bh1 = *reinterpret_cast<const uint32_t*>(whi + roff + 16);
                uint32_t bl0 = *reinterpret_cast<const uint32_t*>(wlo + roff);
                uint32_t bl1 = *reinterpret_cast<const uint32_t*>(wlo + roff + 16);
                mma16816(d[j], ahi, bh0, bh1);   // hi*hi
                mma16816(d[j], ahi, bl0, bl1);   // hi*lo
                mma16816(d[j], alo, bh0, bh1);   // lo*hi
            }
        }
        __syncthreads();
        if (c + 1 < NCHUNK) {
            store_chunk(s ^ 1, wreg);
            __syncthreads();
        }
    }

    // ---- epilogue: spill D to SMEM (aliases W stages), per-lane top-k ------
    __syncthreads();
    float* lw = reinterpret_cast<float*>(sm) + wid * 16 * LROW;
#pragma unroll
    for (int j = 0; j < 8; j++) {
        int col = j * 8 + cp;
        lw[rA * LROW + col]           = d[j][0];
        lw[rA * LROW + col + 1]       = d[j][1];
        lw[(rA + 8) * LROW + col]     = d[j][2];
        lw[(rA + 8) * LROW + col + 1] = d[j][3];
    }
    __syncwarp();

    if (lane < 16) {
        const int tok = wtok + lane;
        const float* row = lw + lane * LROW;
        const float NEG = -3.0e38f;

        float val[9]; int idx[9];
#pragma unroll
        for (int j = 0; j < 9; j++) { val[j] = NEG; idx[j] = 0; }

#pragma unroll
        for (int e = 0; e < N_EXP; e++) {
            float cv = row[e] * SCALE + bias_sm[e];
            int   ci = e;
#pragma unroll
            for (int j = 0; j < 9; j++) {
                if (cv > val[j]) {
                    float tv = val[j]; val[j] = cv; cv = tv;
                    int   ti = idx[j]; idx[j] = ci; ci = ti;
                }
            }
        }

        float ming = val[0] - val[1];
#pragma unroll
        for (int j = 1; j < 8; j++) ming = fminf(ming, val[j] - val[j + 1]);

        float orig[TOP_K];
#pragma unroll
        for (int j = 0; j < TOP_K; j++) orig[j] = val[j] - bias_sm[idx[j]];
        float m = orig[0];
#pragma unroll
        for (int j = 1; j < TOP_K; j++) m = fmaxf(m, orig[j]);
        float ex[TOP_K], ssum = 0.0f;
#pragma unroll
        for (int j = 0; j < TOP_K; j++) { ex[j] = __expf(orig[j] - m); ssum += ex[j]; }
        float inv = 1.0f / ssum;

        float* wout = out + (size_t)tok * TOP_K;
        float* iout = out + (size_t)T * TOP_K + (size_t)tok * TOP_K;
#pragma unroll
        for (int j = 0; j < TOP_K; j++) { wout[j] = ex[j] * inv; iout[j] = (float)idx[j]; }

        if (ming < EPS) {
            int p = atomicAdd(&g_flag_count, 1);
            if (p < MAX_T) g_flags[p] = tok;
        }
    }
}

// ---------------------------------------------------------------------------
// Fixup: exact recompute for flagged near-tie tokens. Reproduces the
// reference-matching blocked fp32 chain (4 panels of 512, serial FFMA
// ascending k, panels added ascending, fmul by scale) + exact top-k/softmax.
// ---------------------------------------------------------------------------
__global__ void __launch_bounds__(256) fixup_kernel(
    const float* __restrict__ x, const float* __restrict__ W,
    const float* __restrict__ bias, float* __restrict__ out, int T)
{
    __shared__ float part[4][N_EXP];
    __shared__ float slog[N_EXP];
    __shared__ float sbia[N_EXP];

    const int t = threadIdx.x;
    const int e = t & 63;
    const int p = t >> 6;

    for (int slot = blockIdx.x; slot < g_flag_count && slot < MAX_T; slot += gridDim.x) {
        const int tok = g_flags[slot];

        const float* xp = x + (size_t)tok * D_MODEL + p * 512;
        const float* wp = W + (size_t)e * D_MODEL + p * 512;
        float acc = 0.0f;
#pragma unroll 8
        for (int i = 0; i < 512; i++)
            acc = __fmaf_rn(xp[i], wp[i], acc);
        part[p][e] = acc;
        __syncthreads();

        if (t < N_EXP) {
            float tot = 0.0f;
#pragma unroll
            for (int pp = 0; pp < 4; pp++) tot = __fadd_rn(tot, part[pp][t]);
            float lg = __fmul_rn(tot, SCALE);
            slog[t] = lg;
            sbia[t] = __fadd_rn(lg, bias[t]);
        }
        __syncthreads();

        if (t == 0) {
            int sel[TOP_K]; float sl[TOP_K];
            for (int k = 0; k < TOP_K; k++) {
                float best = -3.0e38f; int bi = 0;
                for (int ee = 0; ee < N_EXP; ee++)
                    if (sbia[ee] > best) { best = sbia[ee]; bi = ee; }
                sel[k] = bi; sl[k] = slog[bi];
                sbia[bi] = -3.0e38f;
            }
            float m = sl[0];
            for (int k = 1; k < TOP_K; k++) m = fmaxf(m, sl[k]);
            float ex[TOP_K], s = 0.0f;
            for (int k = 0; k < TOP_K; k++) { ex[k] = __expf(sl[k] - m); s += ex[k]; }
            float inv = 1.0f / s;
            for (int k = 0; k < TOP_K; k++) {
                out[(size_t)tok * TOP_K + k] = ex[k] * inv;
                out[(size_t)T * TOP_K + (size_t)tok * TOP_K + k] = (float)sel[k];
            }
        }
        __syncthreads();
    }
}

// ---------------------------------------------------------------------------
extern "C" void kernel_launch(void* const* d_in, const int* in_sizes, int n_in,
                              void* d_out, int out_size)
{
    const float* x    = (const float*)d_in[0];
    const float* W    = (const float*)d_in[1];
    const float* bias = (const float*)d_in[2];
    float* out        = (float*)d_out;

    int T = in_sizes[0] / D_MODEL;  // 16384

    zero_flags_kernel<<<1, 1>>>();
    router_mma_kernel<<<T / CTA_TOK, 256>>>(x, W, bias, out, T);
    fixup_kernel<<<512, 256>>>(x, W, bias, out, T);
}

// round 7
// speedup vs baseline: 1.3690x; 1.3690x over previous
#include <cuda_runtime.h>
#include <cuda_fp16.h>
#include <cstdint>
#include <math.h>

#define D_MODEL 2048
#define N_EXP   64
#define TOP_K   8
#define SCALE   0.022097086912079608f
#define EPS     3.5e-5f
#define MAX_T   16384
#define CTA_TOK 128
#define NCHUNK  32            // 2048 / 64
#define WROWB   144           // padded bytes per 64-half W smem row
#define LROW    66

// ---- device globals (no allocations allowed) --------------------------------
__device__ __half gWhi[N_EXP * D_MODEL];
__device__ __half gWlo[N_EXP * D_MODEL];   // scaled by 2048 (keeps fp16 normal)
__device__ int    g_flag_count;
__device__ int    g_flags[MAX_T];

// ---- fp16 MMA ---------------------------------------------------------------
static __device__ __forceinline__ void mma16816(float* d, const uint32_t* a,
                                                uint32_t b0, uint32_t b1) {
    asm volatile(
        "mma.sync.aligned.m16n8k16.row.col.f32.f16.f16.f32 "
        "{%0,%1,%2,%3}, {%4,%5,%6,%7}, {%8,%9}, {%0,%1,%2,%3};"
        : "+f"(d[0]), "+f"(d[1]), "+f"(d[2]), "+f"(d[3])
        : "r"(a[0]), "r"(a[1]), "r"(a[2]), "r"(a[3]), "r"(b0), "r"(b1));
}

// ---------------------------------------------------------------------------
// Prep: split W (fp32) into fp16 hi + fp16 lo*2048 planes; zero flag count.
// ---------------------------------------------------------------------------
__global__ void __launch_bounds__(256) prep_kernel(const float* __restrict__ W)
{
    if (blockIdx.x == 0 && threadIdx.x == 0) g_flag_count = 0;
    int t = blockIdx.x * 256 + threadIdx.x;   // 16384 threads x 8 elems
#pragma unroll
    for (int u = 0; u < 2; u++) {
        int base = t * 8 + u * 4;
        float4 w = *reinterpret_cast<const float4*>(W + base);
        __half h0 = __float2half_rn(w.x), h1 = __float2half_rn(w.y);
        __half h2 = __float2half_rn(w.z), h3 = __float2half_rn(w.w);
        gWhi[base + 0] = h0; gWhi[base + 1] = h1;
        gWhi[base + 2] = h2; gWhi[base + 3] = h3;
        gWlo[base + 0] = __float2half_rn((w.x - __half2float(h0)) * 2048.0f);
        gWlo[base + 1] = __float2half_rn((w.y - __half2float(h1)) * 2048.0f);
        gWlo[base + 2] = __float2half_rn((w.z - __half2float(h2)) * 2048.0f);
        gWlo[base + 3] = __float2half_rn((w.w - __half2float(h3)) * 2048.0f);
    }
}

// ---------------------------------------------------------------------------
// Main: x(fp16) x [Whi,Wlo] HMMA, 2 passes, fused top-9 / flag / softmax.
// 8 warps; warp = 16 tokens x 64 experts. A chunk-prefetched in regs,
// W double-buffered in SMEM (144B rows -> conflict-free b-frag LDS).
// Staging: 32 B per thread per plane (two uint4) — full 8 KB plane coverage.
// ---------------------------------------------------------------------------
__global__ void __launch_bounds__(256, 1)
router_mma_kernel(const float* __restrict__ x, const float* __restrict__ bias,
                  float* __restrict__ out, int T)
{
    __shared__ __align__(16) char smW[2][2][64 * WROWB];  // [buf][hi/lo]
    __shared__ float bias_sm[N_EXP];

    const int tid  = threadIdx.x;
    const int wid  = tid >> 5;
    const int lane = tid & 31;
    const int tokBase = blockIdx.x * CTA_TOK;
    const int wtok = tokBase + wid * 16;

    if (tid < N_EXP) bias_sm[tid] = bias[tid];

    const int n4 = lane >> 2;          // frag row / b-col
    const int q4 = lane & 3;
    const int cp2 = q4 << 1;

    const float* xA = x + (size_t)(wtok + n4) * D_MODEL;
    const float* xB = x + (size_t)(wtok + n4 + 8) * D_MODEL;

    // W stage: thread -> expert e=tid>>2, 16-half segment q=tid&3 per plane
    const int wge = (tid >> 2) * D_MODEL + (tid & 3) * 16;  // element offset
    const int wse = (tid >> 2) * WROWB + (tid & 3) * 32;    // byte offset

    auto loadA = [&](int c, float2* f) {
#pragma unroll
        for (int ks = 0; ks < 4; ks++) {
            int kb = c * 64 + ks * 16;
            f[ks * 4 + 0] = *reinterpret_cast<const float2*>(xA + kb + cp2);
            f[ks * 4 + 1] = *reinterpret_cast<const float2*>(xB + kb + cp2);
            f[ks * 4 + 2] = *reinterpret_cast<const float2*>(xA + kb + cp2 + 8);
            f[ks * 4 + 3] = *reinterpret_cast<const float2*>(xB + kb + cp2 + 8);
        }
    };
    auto loadW = [&](int c, uint4* h, uint4* l) {
        h[0] = *reinterpret_cast<const uint4*>(&gWhi[wge + c * 64]);
        h[1] = *reinterpret_cast<const uint4*>(&gWhi[wge + c * 64 + 8]);
        l[0] = *reinterpret_cast<const uint4*>(&gWlo[wge + c * 64]);
        l[1] = *reinterpret_cast<const uint4*>(&gWlo[wge + c * 64 + 8]);
    };
    auto storeW = [&](int buf, const uint4* h, const uint4* l) {
        *reinterpret_cast<uint4*>(&smW[buf][0][wse])      = h[0];
        *reinterpret_cast<uint4*>(&smW[buf][0][wse + 16]) = h[1];
        *reinterpret_cast<uint4*>(&smW[buf][1][wse])      = l[0];
        *reinterpret_cast<uint4*>(&smW[buf][1][wse + 16]) = l[1];
    };

    // prologue
    float2 f[16];
    uint4 wh[2], wl[2];
    loadW(0, wh, wl);
    storeW(0, wh, wl);
    loadA(0, f);
    __syncthreads();

    float dh[8][4], dl[8][4];
#pragma unroll
    for (int j = 0; j < 8; j++)
#pragma unroll
        for (int q = 0; q < 4; q++) { dh[j][q] = 0.0f; dl[j][q] = 0.0f; }

    for (int c = 0; c < NCHUNK; c++) {
        const int buf = c & 1;

        // convert current A chunk to fp16x2 fragments
        uint32_t a[16];
#pragma unroll
        for (int i = 0; i < 16; i++) {
            __half2 h = __floats2half2_rn(f[i].x, f[i].y);
            a[i] = *reinterpret_cast<uint32_t*>(&h);
        }
        // prefetch next chunk (A regs + W regs)
        if (c + 1 < NCHUNK) {
            loadA(c + 1, f);
            loadW(c + 1, wh, wl);
        }

        const char* WH = smW[buf][0];
        const char* WL = smW[buf][1];
#pragma unroll
        for (int ks = 0; ks < 4; ks++) {
            const uint32_t cbase = (uint32_t)(ks * 32 + q4 * 4);
#pragma unroll
            for (int j = 0; j < 8; j++) {
                uint32_t ro = (uint32_t)(j * 8 + n4) * WROWB + cbase;
                uint32_t bh0 = *reinterpret_cast<const uint32_t*>(WH + ro);
                uint32_t bh1 = *reinterpret_cast<const uint32_t*>(WH + ro + 16);
                uint32_t bl0 = *reinterpret_cast<const uint32_t*>(WL + ro);
                uint32_t bl1 = *reinterpret_cast<const uint32_t*>(WL + ro + 16);
                mma16816(dh[j], &a[ks * 4], bh0, bh1);
                mma16816(dl[j], &a[ks * 4], bl0, bl1);
            }
        }
        __syncthreads();
        if (c + 1 < NCHUNK) {
            storeW(buf ^ 1, wh, wl);
            __syncthreads();
        }
    }

    // ---- epilogue: spill combined logits to SMEM (aliases smW) -------------
    float* lw = reinterpret_cast<float*>(&smW[0][0][0]) + wid * 16 * LROW;
#pragma unroll
    for (int j = 0; j < 8; j++) {
        int col = j * 8 + cp2;
        const float inv = 1.0f / 2048.0f;
        lw[n4 * LROW + col]           = dh[j][0] + dl[j][0] * inv;
        lw[n4 * LROW + col + 1]       = dh[j][1] + dl[j][1] * inv;
        lw[(n4 + 8) * LROW + col]     = dh[j][2] + dl[j][2] * inv;
        lw[(n4 + 8) * LROW + col + 1] = dh[j][3] + dl[j][3] * inv;
    }
    __syncwarp();

    if (lane < 16) {
        const int tok = wtok + lane;
        const float* row = lw + lane * LROW;
        const float NEG = -3.0e38f;

        float val[9]; int idx[9];
#pragma unroll
        for (int j = 0; j < 9; j++) { val[j] = NEG; idx[j] = 0; }

#pragma unroll
        for (int e = 0; e < N_EXP; e++) {
            float cv = row[e] * SCALE + bias_sm[e];
            int   ci = e;
#pragma unroll
            for (int j = 0; j < 9; j++) {
                if (cv > val[j]) {
                    float tv = val[j]; val[j] = cv; cv = tv;
                    int   ti = idx[j]; idx[j] = ci; ci = ti;
                }
            }
        }

        float ming = val[0] - val[1];
#pragma unroll
        for (int j = 1; j < 8; j++) ming = fminf(ming, val[j] - val[j + 1]);

        float orig[TOP_K];
#pragma unroll
        for (int j = 0; j < TOP_K; j++) orig[j] = val[j] - bias_sm[idx[j]];
        float m = orig[0];
#pragma unroll
        for (int j = 1; j < TOP_K; j++) m = fmaxf(m, orig[j]);
        float ex[TOP_K], ssum = 0.0f;
#pragma unroll
        for (int j = 0; j < TOP_K; j++) { ex[j] = __expf(orig[j] - m); ssum += ex[j]; }
        float inv = 1.0f / ssum;

        float* wout = out + (size_t)tok * TOP_K;
        float* iout = out + (size_t)T * TOP_K + (size_t)tok * TOP_K;
#pragma unroll
        for (int j = 0; j < TOP_K; j++) { wout[j] = ex[j] * inv; iout[j] = (float)idx[j]; }

        if (ming < EPS) {
            int p = atomicAdd(&g_flag_count, 1);
            if (p < MAX_T) g_flags[p] = tok;
        }
    }
}

// ---------------------------------------------------------------------------
// Fixup (batched): 16 flagged tokens per CTA iteration; exact reference-
// matching blocked fp32 chain (panels of 512 = 4 staged K-chunks of 128,
// serial FFMA ascending, panels added ascending) + exact top-k/softmax.
// W staged transposed [k][e] in SMEM for LDS.128 of 4 experts.
// ---------------------------------------------------------------------------
#define FB 16
__global__ void __launch_bounds__(256) fixup_kernel(
    const float* __restrict__ x, const float* __restrict__ W,
    const float* __restrict__ bias, float* __restrict__ out, int T)
{
    __shared__ __align__(16) float Wp[128][68];   // 34816 B
    __shared__ float Xp[FB][130];                 //  8320 B
    __shared__ float Lg[FB][66];                  //  4224 B
    __shared__ float bias_f[N_EXP];               //   256 B

    const int t = threadIdx.x;
    if (t < N_EXP) bias_f[t] = bias[t];

    int F = g_flag_count;
    if (F > MAX_T) F = MAX_T;
    if (F == 0) return;
    const int nb = (F + FB - 1) / FB;

    const int tk = t >> 4;          // token slot 0..15
    const int e0 = (t & 15) * 4;    // 4 experts per thread
    const int xe = t & 63, xg = (t >> 6) * 32;   // W stage mapping
    const int stk = t >> 4, skk = (t & 15) * 8;  // X stage mapping

    for (int b = blockIdx.x; b < nb; b += gridDim.x) {
        float accT[4] = {0.f, 0.f, 0.f, 0.f};
        float accP[4] = {0.f, 0.f, 0.f, 0.f};

        for (int kc = 0; kc < 16; kc++) {
            __syncthreads();   // prior iteration done with Xp/Wp/Lg
            // stage X chunk
            {
                int s2 = b * FB + stk;
                int gt = g_flags[(s2 < F) ? s2 : (F - 1)];
                const float* xp = x + (size_t)gt * D_MODEL + kc * 128 + skk;
                float4 v0 = *reinterpret_cast<const float4*>(xp);
                float4 v1 = *reinterpret_cast<const float4*>(xp + 4);
                Xp[stk][skk + 0] = v0.x; Xp[stk][skk + 1] = v0.y;
                Xp[stk][skk + 2] = v0.z; Xp[stk][skk + 3] = v0.w;
                Xp[stk][skk + 4] = v1.x; Xp[stk][skk + 5] = v1.y;
                Xp[stk][skk + 6] = v1.z; Xp[stk][skk + 7] = v1.w;
            }
            // stage W chunk transposed
#pragma unroll
            for (int u = 0; u < 32; u += 4) {
                float4 w = *reinterpret_cast<const float4*>(
                    W + (size_t)xe * D_MODEL + kc * 128 + xg + u);
                Wp[xg + u + 0][xe] = w.x;
                Wp[xg + u + 1][xe] = w.y;
                Wp[xg + u + 2][xe] = w.z;
                Wp[xg + u + 3][xe] = w.w;
            }
            __syncthreads();
            // exact serial chain, ascending k
#pragma unroll 4
            for (int k = 0; k < 128; k++) {
                float xv = Xp[tk][k];
                float4 wv = *reinterpret_cast<const float4*>(&Wp[k][e0]);
                accP[0] = __fmaf_rn(xv, wv.x, accP[0]);
                accP[1] = __fmaf_rn(xv, wv.y, accP[1]);
                accP[2] = __fmaf_rn(xv, wv.z, accP[2]);
                accP[3] = __fmaf_rn(xv, wv.w, accP[3]);
            }
            if ((kc & 3) == 3) {     // panel (512) boundary
#pragma unroll
                for (int q = 0; q < 4; q++) {
                    accT[q] = __fadd_rn(accT[q], accP[q]);
                    accP[q] = 0.0f;
                }
            }
        }
#pragma unroll
        for (int q = 0; q < 4; q++)
            Lg[tk][e0 + q] = __fmul_rn(accT[q], SCALE);
        __syncthreads();

        if (t < FB && b * FB + t < F) {
            const int tok = g_flags[b * FB + t];
            unsigned long long used = 0ull;
            int sel[TOP_K]; float sl[TOP_K];
            for (int k = 0; k < TOP_K; k++) {
                float best = -3.0e38f; int bi = 0;
                for (int e = 0; e < N_EXP; e++) {
                    if ((used >> e) & 1ull) continue;
                    float bv = __fadd_rn(Lg[t][e], bias_f[e]);
                    if (bv > best) { best = bv; bi = e; }
                }
                sel[k] = bi; sl[k] = Lg[t][bi];
                used |= (1ull << bi);
            }
            float m = sl[0];
            for (int k = 1; k < TOP_K; k++) m = fmaxf(m, sl[k]);
            float ex[TOP_K], s = 0.0f;
            for (int k = 0; k < TOP_K; k++) { ex[k] = __expf(sl[k] - m); s += ex[k]; }
            float inv = 1.0f / s;
            for (int k = 0; k < TOP_K; k++) {
                out[(size_t)tok * TOP_K + k] = ex[k] * inv;
                out[(size_t)T * TOP_K + (size_t)tok * TOP_K + k] = (float)sel[k];
            }
        }
    }
}

// ---------------------------------------------------------------------------
extern "C" void kernel_launch(void* const* d_in, const int* in_sizes, int n_in,
                              void* d_out, int out_size)
{
    const float* x    = (const float*)d_in[0];
    const float* W    = (const float*)d_in[1];
    const float* bias = (const float*)d_in[2];
    float* out        = (float*)d_out;

    int T = in_sizes[0] / D_MODEL;  // 16384

    prep_kernel<<<64, 256>>>(W);
    router_mma_kernel<<<T / CTA_TOK, 256>>>(x, bias, out, T);
    fixup_kernel<<<592, 256>>>(x, W, bias, out, T);
}